// round 4
// baseline (speedup 1.0000x reference)
#include <cuda_runtime.h>
#include <cstdint>

#define NV 4000
#define NE 16000
#define DD 64
#define NSPLIT 9
#define NKBLK 500      /* 16000 / 32 */
#define BK 32
#define BSTRIDE 72     /* padded smem row stride (floats) -> conflict-free frags */

// ---------------- device scratch (no allocation allowed) ----------------
__device__ float g_x1e[NE * DD];                 // 4 MB: per-edge x_e @ W1[ord]
__device__ float g_sv[DD];                       // colsum of x_v
__device__ float g_se[5 * DD];                   // per-order colsums of x_e
__device__ float g_x0b[DD];                      // x0 + b (precombined)
__device__ float g_csplit[(size_t)NSPLIT * NV * DD];  // 9.2 MB split-K partials

// ---------------- helpers ----------------
__device__ __forceinline__ uint32_t tf32_cvt(float x) {
    uint32_t u;
    asm("cvt.rna.tf32.f32 %0, %1;" : "=r"(u) : "f"(x));
    return u;
}

__device__ __forceinline__ void mma_tf32(float c[4],
                                         uint32_t a0, uint32_t a1, uint32_t a2, uint32_t a3,
                                         uint32_t b0, uint32_t b1) {
    asm volatile(
        "mma.sync.aligned.m16n8k8.row.col.f32.tf32.tf32.f32 "
        "{%0,%1,%2,%3},{%4,%5,%6,%7},{%8,%9},{%0,%1,%2,%3};"
        : "+f"(c[0]), "+f"(c[1]), "+f"(c[2]), "+f"(c[3])
        : "r"(a0), "r"(a1), "r"(a2), "r"(a3), "r"(b0), "r"(b1));
}

// ---------------- kernel 0: zero the reduction scratch ----------------
__global__ void zero_kernel() {
    int t = threadIdx.x;
    if (t < DD) g_sv[t] = 0.f;
    else g_se[t - DD] = 0.f;   // 64..383 -> 320 entries
}

// ---------------- kernel 1: column-sum of x_v ----------------
__global__ void vreduce_kernel(const float* __restrict__ xv) {
    __shared__ float red[256];
    int tid = threadIdx.x;
    int j = tid & 63, rg = tid >> 6;          // 4 row groups x 64 cols
    int base = blockIdx.x * 128;
    float a = 0.f;
#pragma unroll 8
    for (int k = 0; k < 32; k++) {
        int r = base + 4 * k + rg;
        if (r < NV) a += xv[r * DD + j];
    }
    red[tid] = a;
    __syncthreads();
    if (tid < DD) {
        float s = red[tid] + red[tid + 64] + red[tid + 128] + red[tid + 192];
        atomicAdd(&g_sv[tid], s);
    }
}

// ---------------- kernel 2: x1_e = x_e @ W1[ord], plus per-order colsums ----------------
// 16 edges / block, 16 threads / edge, float4 over j.
__global__ void edge_kernel(const float* __restrict__ xe,
                            const int* __restrict__ orders,
                            const float* __restrict__ W) {
    __shared__ float xesh[16 * DD];
    __shared__ int   osh[16];
    __shared__ float accsh[5 * DD];
    int tid = threadIdx.x;
    int e0 = blockIdx.x * 16;

    if (tid < 320) accsh[tid] = 0.f;
    // stage 16 edge rows (1024 floats) as float4
    reinterpret_cast<float4*>(xesh)[tid] =
        reinterpret_cast<const float4*>(xe + (size_t)e0 * DD)[tid];
    if (tid < 16) osh[tid] = orders[e0 + tid];
    __syncthreads();

    int el = tid >> 4;     // edge within block
    int jt = tid & 15;     // j-quad
    int ord = osh[el];
    const float4* Wp = reinterpret_cast<const float4*>(W + (size_t)(5 + ord) * 4096);

    float4 acc = make_float4(0.f, 0.f, 0.f, 0.f);
#pragma unroll 8
    for (int i = 0; i < DD; i++) {
        float x = xesh[el * DD + i];
        float4 w = __ldg(Wp + i * 16 + jt);
        acc.x = fmaf(x, w.x, acc.x);
        acc.y = fmaf(x, w.y, acc.y);
        acc.z = fmaf(x, w.z, acc.z);
        acc.w = fmaf(x, w.w, acc.w);
    }
    reinterpret_cast<float4*>(g_x1e)[(size_t)(e0 + el) * 16 + jt] = acc;

    // block-local per-order colsum of x_e, then one flush to global
#pragma unroll
    for (int c = 0; c < 4; c++)
        atomicAdd(&accsh[ord * DD + jt * 4 + c], xesh[el * DD + jt * 4 + c]);
    __syncthreads();
    if (tid < 320) atomicAdd(&g_se[tid], accsh[tid]);
}

// ---------------- kernel 3: x0 + b (tiny) ----------------
__global__ void x0_kernel(const float* __restrict__ W, const float* __restrict__ b) {
    int j = threadIdx.x;   // 64 threads
    float acc = 0.f;
#pragma unroll 8
    for (int i = 0; i < DD; i++)
        acc = fmaf(g_sv[i], W[4096 + i * DD + j], acc);      // W[0][1]
#pragma unroll
    for (int k = 0; k < 5; k++) {
#pragma unroll 8
        for (int i = 0; i < DD; i++)
            acc = fmaf(g_se[k * DD + i], W[(size_t)k * 4096 + i * DD + j], acc);  // W[0][k]
    }
    g_x0b[j] = acc * (1.0f / 20000.0f) + b[j];
}

// ---------------- kernel 4: split-K tf32 GEMM  C = incidence @ x1_e ----------------
#define LOAD_A(dst, kb) do {                                                 \
    _Pragma("unroll")                                                        \
    for (int q = 0; q < 4; q++) {                                            \
        int c = (kb) + q * 8 + tig;                                          \
        dst[q*4+0]      = v00 ? __ldg(p00 + c)     : 0.f;                    \
        dst[q*4+1]      = v01 ? __ldg(p01 + c)     : 0.f;                    \
        dst[q*4+2]      = v00 ? __ldg(p00 + c + 4) : 0.f;                    \
        dst[q*4+3]      = v01 ? __ldg(p01 + c + 4) : 0.f;                    \
        dst[16+q*4+0]   = v10 ? __ldg(p10 + c)     : 0.f;                    \
        dst[16+q*4+1]   = v11 ? __ldg(p11 + c)     : 0.f;                    \
        dst[16+q*4+2]   = v10 ? __ldg(p10 + c + 4) : 0.f;                    \
        dst[16+q*4+3]   = v11 ? __ldg(p11 + c + 4) : 0.f;                    \
    }                                                                        \
} while (0)

__global__ void __launch_bounds__(128)
gemm_kernel(const float* __restrict__ inc) {
    __shared__ float Bs[2][BK * BSTRIDE];

    int tid  = threadIdx.x;
    int warp = tid >> 5, lane = tid & 31;
    int g    = lane >> 2, tig = lane & 3;
    int tile = blockIdx.x, split = blockIdx.y;

    int b0 = (split * NKBLK) / NSPLIT;
    int b1 = ((split + 1) * NKBLK) / NSPLIT;
    int niter = b1 - b0;
    int kbase = b0 * BK;

    int rowbase = tile * 128 + warp * 16;
    int r00 = rowbase + g, r01 = r00 + 8, r10 = r00 + 64, r11 = r00 + 72;
    bool v00 = r00 < NV, v01 = r01 < NV, v10 = r10 < NV, v11 = r11 < NV;
    const float* p00 = inc + (size_t)r00 * NE;
    const float* p01 = inc + (size_t)r01 * NE;
    const float* p10 = inc + (size_t)r10 * NE;
    const float* p11 = inc + (size_t)r11 * NE;

    int brow = tid >> 4;   // 0..7 (+8 per chunk)
    int bc4  = tid & 15;

    float Aa[32], An[32];
    float Creg[2][8][4];
#pragma unroll
    for (int m = 0; m < 2; m++)
#pragma unroll
        for (int n8 = 0; n8 < 8; n8++)
#pragma unroll
            for (int c = 0; c < 4; c++) Creg[m][n8][c] = 0.f;

    // ---- prologue: A(0) into regs, B(0) into Bs[0] (tf32-rounded) ----
    LOAD_A(Aa, kbase);
#pragma unroll
    for (int cc = 0; cc < 4; cc++) {
        float4 t = __ldg(reinterpret_cast<const float4*>(
                         g_x1e + (size_t)(kbase + brow + 8 * cc) * DD) + bc4);
        float* d = &Bs[0][(brow + 8 * cc) * BSTRIDE + bc4 * 4];
        d[0] = __uint_as_float(tf32_cvt(t.x));
        d[1] = __uint_as_float(tf32_cvt(t.y));
        d[2] = __uint_as_float(tf32_cvt(t.z));
        d[3] = __uint_as_float(tf32_cvt(t.w));
    }
    __syncthreads();

    for (int it = 0; it < niter; ++it) {
        bool hasnext = (it + 1) < niter;
        float4 Bp[4];
        if (hasnext) {
            int kb = kbase + (it + 1) * BK;
            LOAD_A(An, kb);
#pragma unroll
            for (int cc = 0; cc < 4; cc++)
                Bp[cc] = __ldg(reinterpret_cast<const float4*>(
                               g_x1e + (size_t)(kb + brow + 8 * cc) * DD) + bc4);
        }

        const float* Bcur = Bs[it & 1];
#pragma unroll
        for (int q = 0; q < 4; q++) {
            uint32_t bf0[8], bf1[8];
            int kr = q * 8 + tig;
#pragma unroll
            for (int n8 = 0; n8 < 8; n8++) {
                bf0[n8] = __float_as_uint(Bcur[kr * BSTRIDE + n8 * 8 + g]);
                bf1[n8] = __float_as_uint(Bcur[(kr + 4) * BSTRIDE + n8 * 8 + g]);
            }
#pragma unroll
            for (int m = 0; m < 2; m++) {
                uint32_t a0 = tf32_cvt(Aa[m * 16 + q * 4 + 0]);
                uint32_t a1 = tf32_cvt(Aa[m * 16 + q * 4 + 1]);
                uint32_t a2 = tf32_cvt(Aa[m * 16 + q * 4 + 2]);
                uint32_t a3 = tf32_cvt(Aa[m * 16 + q * 4 + 3]);
#pragma unroll
                for (int n8 = 0; n8 < 8; n8++)
                    mma_tf32(Creg[m][n8], a0, a1, a2, a3, bf0[n8], bf1[n8]);
            }
        }

        if (hasnext) {
            float* d = Bs[(it + 1) & 1];
#pragma unroll
            for (int cc = 0; cc < 4; cc++) {
                float* dst = d + (brow + 8 * cc) * BSTRIDE + bc4 * 4;
                dst[0] = __uint_as_float(tf32_cvt(Bp[cc].x));
                dst[1] = __uint_as_float(tf32_cvt(Bp[cc].y));
                dst[2] = __uint_as_float(tf32_cvt(Bp[cc].z));
                dst[3] = __uint_as_float(tf32_cvt(Bp[cc].w));
            }
            __syncthreads();
#pragma unroll
            for (int i = 0; i < 32; i++) Aa[i] = An[i];
        }
    }

    // ---- store split partials ----
#pragma unroll
    for (int m = 0; m < 2; m++) {
#pragma unroll
        for (int part = 0; part < 2; part++) {
            int row = rowbase + m * 64 + part * 8 + g;
            if (row < NV) {
                float* op = g_csplit + ((size_t)split * NV + row) * DD + tig * 2;
#pragma unroll
                for (int n8 = 0; n8 < 8; n8++) {
                    float2 v2 = make_float2(Creg[m][n8][part * 2],
                                            Creg[m][n8][part * 2 + 1]);
                    *reinterpret_cast<float2*>(op + n8 * 8) = v2;
                }
            }
        }
    }
}

// ---------------- kernel 5: epilogue (split-K reduce + x_v@W11 + scale + x0 + b) ----------------
__global__ void __launch_bounds__(256)
epilogue_kernel(const float* __restrict__ xv,
                const float* __restrict__ sn,
                const float* __restrict__ W,
                float* __restrict__ out) {
    __shared__ float Wsh[DD * DD];
    __shared__ float xvsh[4 * DD];
    int tid = threadIdx.x;
    int r0 = blockIdx.x * 4;
    int rloc = tid >> 6, j = tid & 63;
    int row = r0 + rloc;

    const float4* W4 = reinterpret_cast<const float4*>(W + 6 * 4096);  // W[1][1]
#pragma unroll
    for (int c = 0; c < 4; c++)
        reinterpret_cast<float4*>(Wsh)[tid + 256 * c] = __ldg(W4 + tid + 256 * c);
    if (tid < 64)
        reinterpret_cast<float4*>(xvsh)[tid] =
            __ldg(reinterpret_cast<const float4*>(xv + (size_t)r0 * DD) + tid);
    __syncthreads();

    float acc = 0.f;
#pragma unroll 8
    for (int i = 0; i < DD; i++)
        acc = fmaf(xvsh[rloc * DD + i], Wsh[i * DD + j], acc);

    float csum = 0.f;
#pragma unroll
    for (int s = 0; s < NSPLIT; s++)
        csum += g_csplit[((size_t)s * NV + row) * DD + j];

    float rinv = 1.0f / (1.0f + __ldg(sn + row));
    out[(size_t)row * DD + j] = (acc + csum) * rinv + g_x0b[j];
}

// ---------------- launch ----------------
extern "C" void kernel_launch(void* const* d_in, const int* in_sizes, int n_in,
                              void* d_out, int out_size) {
    const float* x_v    = (const float*)d_in[0];
    const float* x_e    = (const float*)d_in[1];
    const float* inc    = (const float*)d_in[2];
    const int*   orders = (const int*)  d_in[3];
    const float* sn     = (const float*)d_in[4];
    const float* W      = (const float*)d_in[5];
    const float* b      = (const float*)d_in[6];
    float*       out    = (float*)d_out;

    zero_kernel   <<<1, 384>>>();
    vreduce_kernel<<<32, 256>>>(x_v);
    edge_kernel   <<<NE / 16, 256>>>(x_e, orders, W);
    x0_kernel     <<<1, 64>>>(W, b);
    dim3 ggrid(32, NSPLIT);
    gemm_kernel   <<<ggrid, 128>>>(inc);
    epilogue_kernel<<<NV / 4, 256>>>(x_v, sn, W, out);
}